// round 6
// baseline (speedup 1.0000x reference)
#include <cuda_runtime.h>
#include <math.h>

#define BATCH  8
#define NPTS   4096
#define HH     256
#define KOUT   1024
#define NC     63
#define NBLK   128          // scatter/hist blocks total
#define SLICES 16           // blocks per batch
#define SL_N   256          // points per slice == blockDim

// Scratch (__device__ globals: allowed under allocation guards)
__device__ int    g_parthist[NBLK][NC];   // per-block partial histograms (plain stores)
__device__ int    g_start[BATCH][NC];     // batch-level cluster start
__device__ int    g_cnt  [BATCH][NC];     // batch-level cluster count
__device__ float4 g_kva[BATCH * NPTS];    // sorted (k0*scale, k1*scale, k2*scale, v0)
__device__ float2 g_kvb[BATCH * NPTS];    // sorted (v1, v2)

// ---------------------------------------------------------------------------
// K1: per-block partial histogram. Block blk = b*16+sl owns 256 points.
// ---------------------------------------------------------------------------
__global__ __launch_bounds__(SL_N)
void hist_kernel(const int* __restrict__ labels)
{
    __shared__ int s_hist[NC];
    const int tid = threadIdx.x;
    const int blk = blockIdx.x;
    if (tid < NC) s_hist[tid] = 0;
    __syncthreads();
    const int l = labels[blk * SL_N + tid];   // blk*256+tid == b*4096 + sl*256 + tid
    if (l >= 0) atomicAdd(&s_hist[l], 1);
    __syncthreads();
    if (tid < NC) g_parthist[blk][tid] = s_hist[tid];   // exclusive slot
}

// ---------------------------------------------------------------------------
// K2: prefix (per block, from partials) + scatter projected k/v into sorted
// packed arrays. Cursor arithmetic is block-local (smem atomics only).
// ---------------------------------------------------------------------------
__global__ __launch_bounds__(SL_N)
void scatter_kernel(const float* __restrict__ x,
                    const int*   __restrict__ labels,
                    const float* __restrict__ Wk, const float* __restrict__ bk,
                    const float* __restrict__ Wv, const float* __restrict__ bv)
{
    __shared__ int s_cnt[NC];     // batch totals
    __shared__ int s_base[NC];    // this block's slice scatter base
    __shared__ int s_cur[NC];     // block-local cursors

    const int tid = threadIdx.x;
    const int blk = blockIdx.x;
    const int b   = blk >> 4;
    const int sl  = blk & 15;

    // Reduce partials for this batch: total + exclusive-lt(sl)
    if (tid < NC) {
        int tot = 0, lt = 0;
#pragma unroll
        for (int j = 0; j < SLICES; j++) {
            int v = g_parthist[b * SLICES + j][tid];
            tot += v;
            if (j < sl) lt += v;
        }
        s_cnt[tid]  = tot;
        s_base[tid] = lt;     // temporarily: sum of earlier slices
        s_cur[tid]  = 0;
    }

    // projection weights (broadcast)
    float wk[9], wv[9], bk3[3], bv3[3];
#pragma unroll
    for (int i = 0; i < 9; i++) { wk[i] = __ldg(Wk + i); wv[i] = __ldg(Wv + i); }
#pragma unroll
    for (int i = 0; i < 3; i++) { bk3[i] = __ldg(bk + i); bv3[i] = __ldg(bv + i); }

    __syncthreads();
    if (tid == 0) {
        int acc = 0;
#pragma unroll 1
        for (int c = 0; c < NC; c++) {
            int st = acc;
            acc += s_cnt[c];
            s_base[c] += st;          // start[c] + earlier-slice offset
            if (sl == 0) { g_start[b][c] = st; g_cnt[b][c] = s_cnt[c]; }
        }
    }
    __syncthreads();

    const int gidx = blk * SL_N + tid;        // == b*NPTS + sl*256 + tid
    const int l = labels[gidx];
    if (l >= 0) {
        const float* xv = x + (size_t)gidx * 3;
        float x0 = xv[0], x1 = xv[1], x2 = xv[2];
        int pos = s_base[l] + atomicAdd(&s_cur[l], 1);
        int p = b * NPTS + pos;
        const float scale = 0.57735026919f;   // fold 1/sqrt(3) into k
        float k0 = fmaf(wk[0], x0, fmaf(wk[1], x1, fmaf(wk[2], x2, bk3[0]))) * scale;
        float k1 = fmaf(wk[3], x0, fmaf(wk[4], x1, fmaf(wk[5], x2, bk3[1]))) * scale;
        float k2 = fmaf(wk[6], x0, fmaf(wk[7], x1, fmaf(wk[8], x2, bk3[2]))) * scale;
        float v0 = fmaf(wv[0], x0, fmaf(wv[1], x1, fmaf(wv[2], x2, bv3[0])));
        float v1 = fmaf(wv[3], x0, fmaf(wv[4], x1, fmaf(wv[5], x2, bv3[1])));
        float v2 = fmaf(wv[6], x0, fmaf(wv[7], x1, fmaf(wv[8], x2, bv3[2])));
        g_kva[p] = make_float4(k0, k1, k2, v0);
        g_kvb[p] = make_float2(v1, v2);
    }
}

// ---------------------------------------------------------------------------
// K3: warp-per-query attention (plain-exp softmax) + out_proj + MLP.
// 256 threads/block, 8 warps -> 1024 blocks for 8192 queries.
// ---------------------------------------------------------------------------
__global__ __launch_bounds__(256)
void attn_mlp_kernel(const float* __restrict__ x,
                     const int*   __restrict__ labels,
                     const float* __restrict__ Wq, const float* __restrict__ bq,
                     const float* __restrict__ Wo, const float* __restrict__ bo,
                     const float* __restrict__ W1, const float* __restrict__ b1,
                     const float* __restrict__ W2, const float* __restrict__ b2,
                     float* __restrict__ out)
{
    const int tid  = threadIdx.x;
    const int warp = tid >> 5;
    const int lane = tid & 31;
    const int qid  = blockIdx.x * 8 + warp;   // 0..8191
    const int b    = qid >> 10;
    const int n    = qid & 1023;              // first KOUT rows only

    const int l = labels[b * NPTS + n];

    float c0 = 0.f, c1 = 0.f, c2 = 0.f;
    if (l >= 0) {
        const float* xv = x + (size_t)(b * NPTS + n) * 3;
        float x0 = xv[0], x1 = xv[1], x2 = xv[2];
        // q (scale already folded into stored k)
        float q0 = fmaf(__ldg(Wq+0), x0, fmaf(__ldg(Wq+1), x1, fmaf(__ldg(Wq+2), x2, __ldg(bq+0))));
        float q1 = fmaf(__ldg(Wq+3), x0, fmaf(__ldg(Wq+4), x1, fmaf(__ldg(Wq+5), x2, __ldg(bq+1))));
        float q2 = fmaf(__ldg(Wq+6), x0, fmaf(__ldg(Wq+7), x1, fmaf(__ldg(Wq+8), x2, __ldg(bq+2))));

        const int st  = b * NPTS + g_start[b][l];
        const int cnt = g_cnt[b][l];

        // plain-exp softmax (scores O(few): fp32 exp has headroom to 88)
        float sm = 0.f, a0 = 0.f, a1 = 0.f, a2 = 0.f;
        for (int j = lane; j < cnt; j += 32) {
            float4 ka = g_kva[st + j];
            float2 kb = g_kvb[st + j];
            float s = fmaf(q0, ka.x, fmaf(q1, ka.y, q2 * ka.z));
            float e = __expf(s);
            sm += e;
            a0 = fmaf(e, ka.w, a0);
            a1 = fmaf(e, kb.x, a1);
            a2 = fmaf(e, kb.y, a2);
        }
#pragma unroll
        for (int off = 16; off; off >>= 1) {
            sm += __shfl_down_sync(0xffffffffu, sm, off);
            a0 += __shfl_down_sync(0xffffffffu, a0, off);
            a1 += __shfl_down_sync(0xffffffffu, a1, off);
            a2 += __shfl_down_sync(0xffffffffu, a2, off);
        }
        sm = __shfl_sync(0xffffffffu, sm, 0);
        a0 = __shfl_sync(0xffffffffu, a0, 0);
        a1 = __shfl_sync(0xffffffffu, a1, 0);
        a2 = __shfl_sync(0xffffffffu, a2, 0);
        float inv = 1.f / sm;               // sm > 0: query is its own member
        c0 = a0 * inv; c1 = a1 * inv; c2 = a2 * inv;
    }

    // out_proj (redundant per lane; broadcast loads)
    float o0 = fmaf(__ldg(Wo+0), c0, fmaf(__ldg(Wo+1), c1, fmaf(__ldg(Wo+2), c2, __ldg(bo+0))));
    float o1 = fmaf(__ldg(Wo+3), c0, fmaf(__ldg(Wo+4), c1, fmaf(__ldg(Wo+5), c2, __ldg(bo+1))));
    float o2 = fmaf(__ldg(Wo+6), c0, fmaf(__ldg(Wo+7), c1, fmaf(__ldg(Wo+8), c2, __ldg(bo+2))));

    // MLP 3->256->3: 8 hidden units per lane, weights via L1 (hot after warp 0)
    float y0 = 0.f, y1 = 0.f, y2 = 0.f;
#pragma unroll
    for (int t = 0; t < HH / 32; t++) {
        int j = lane + t * 32;
        float h = fmaf(__ldg(W1 + j * 3 + 0), o0,
                  fmaf(__ldg(W1 + j * 3 + 1), o1,
                  fmaf(__ldg(W1 + j * 3 + 2), o2, __ldg(b1 + j))));
        h = fmaxf(h, 0.f);
        y0 = fmaf(__ldg(W2 +          j), h, y0);
        y1 = fmaf(__ldg(W2 + HH     + j), h, y1);
        y2 = fmaf(__ldg(W2 + 2 * HH + j), h, y2);
    }
#pragma unroll
    for (int off = 16; off; off >>= 1) {
        y0 += __shfl_down_sync(0xffffffffu, y0, off);
        y1 += __shfl_down_sync(0xffffffffu, y1, off);
        y2 += __shfl_down_sync(0xffffffffu, y2, off);
    }
    if (lane == 0) {
        float* op = out + (size_t)(b * KOUT + n) * 3;
        op[0] = y0 + __ldg(b2 + 0);
        op[1] = y1 + __ldg(b2 + 1);
        op[2] = y2 + __ldg(b2 + 2);
    }
}

// ---------------------------------------------------------------------------
extern "C" void kernel_launch(void* const* d_in, const int* in_sizes, int n_in,
                              void* d_out, int out_size)
{
    const float* x      = (const float*)d_in[0];
    const int*   labels = (const int*)  d_in[1];
    const float* Wq = (const float*)d_in[2];
    const float* bq = (const float*)d_in[3];
    const float* Wk = (const float*)d_in[4];
    const float* bk = (const float*)d_in[5];
    const float* Wv = (const float*)d_in[6];
    const float* bv = (const float*)d_in[7];
    const float* Wo = (const float*)d_in[8];
    const float* bo = (const float*)d_in[9];
    const float* W1 = (const float*)d_in[10];
    const float* b1 = (const float*)d_in[11];
    const float* W2 = (const float*)d_in[12];
    const float* b2 = (const float*)d_in[13];
    float* out = (float*)d_out;

    hist_kernel<<<NBLK, SL_N>>>(labels);
    scatter_kernel<<<NBLK, SL_N>>>(x, labels, Wk, bk, Wv, bv);
    attn_mlp_kernel<<<(BATCH * KOUT) / 8, 256>>>(x, labels, Wq, bq, Wo, bo,
                                                 W1, b1, W2, b2, out);
}

// round 7
// speedup vs baseline: 1.4516x; 1.4516x over previous
#include <cuda_runtime.h>
#include <math.h>

#define BATCH 8
#define NPTS  4096
#define HH    256
#define KOUT  1024
#define NC    63
#define CAP   1024          // smem member capacity (expected cnt ~65; 16x margin)
#define NCHUNK (NPTS / 256) // 16

// ---------------------------------------------------------------------------
// Single kernel. Block (b,c): c in [0,63) = cluster block, c==63 = noise rows.
// Barrier-free atomic compaction of member x into smem; attention uses
//   score = (Wk^T q)·x + q·bk          (k never materialized)
//   ctx   = Wv·(softmax-weighted mean of x) + bv   (v never materialized)
// ---------------------------------------------------------------------------
__global__ __launch_bounds__(256)
void fused_kernel(const float* __restrict__ x,
                  const int*   __restrict__ labels,
                  const float* __restrict__ Wq, const float* __restrict__ bq,
                  const float* __restrict__ Wk, const float* __restrict__ bk,
                  const float* __restrict__ Wv, const float* __restrict__ bv,
                  const float* __restrict__ Wo, const float* __restrict__ bo,
                  const float* __restrict__ W1, const float* __restrict__ b1,
                  const float* __restrict__ W2, const float* __restrict__ b2,
                  float* __restrict__ out)
{
    __shared__ float4 sx[CAP];           // member x (w unused)
    __shared__ int    sq[CAP];           // member query rows (n < KOUT)
    __shared__ float  sW1[HH * 3], sW2[3 * HH], sb1[HH];
    __shared__ int    s_cnt, s_qn;
    __shared__ float  s_y3[3];

    const int tid  = threadIdx.x;
    const int warp = tid >> 5;
    const int lane = tid & 31;
    const int b    = blockIdx.x >> 6;
    const int c    = blockIdx.x & 63;

    const int*   lab = labels + b * NPTS;
    const float* xb  = x + (size_t)b * NPTS * 3;

    // Stage MLP weights (used by every query in this block)
    for (int i = tid; i < HH * 3; i += 256) { sW1[i] = W1[i]; sW2[i] = W2[i]; }
    for (int i = tid; i < HH; i += 256) sb1[i] = b1[i];

    // ---------------- noise block: constant output for label==-1 rows --------
    if (c == NC) {
        __syncthreads();
        if (warp == 0) {
            float o0 = __ldg(bo + 0), o1 = __ldg(bo + 1), o2 = __ldg(bo + 2);
            float y0 = 0.f, y1 = 0.f, y2 = 0.f;
#pragma unroll
            for (int t = 0; t < HH / 32; t++) {
                int j = lane + t * 32;
                float h = fmaf(sW1[j*3+0], o0, fmaf(sW1[j*3+1], o1, fmaf(sW1[j*3+2], o2, sb1[j])));
                h = fmaxf(h, 0.f);
                y0 = fmaf(sW2[j], h, y0);
                y1 = fmaf(sW2[HH + j], h, y1);
                y2 = fmaf(sW2[2*HH + j], h, y2);
            }
#pragma unroll
            for (int off = 16; off; off >>= 1) {
                y0 += __shfl_down_sync(0xffffffffu, y0, off);
                y1 += __shfl_down_sync(0xffffffffu, y1, off);
                y2 += __shfl_down_sync(0xffffffffu, y2, off);
            }
            if (lane == 0) {
                s_y3[0] = y0 + __ldg(b2 + 0);
                s_y3[1] = y1 + __ldg(b2 + 1);
                s_y3[2] = y2 + __ldg(b2 + 2);
            }
        }
        __syncthreads();
        float y0 = s_y3[0], y1 = s_y3[1], y2 = s_y3[2];
        for (int n = tid; n < KOUT; n += 256) {
            if (lab[n] == -1) {
                float* op = out + (size_t)(b * KOUT + n) * 3;
                op[0] = y0; op[1] = y1; op[2] = y2;
            }
        }
        return;
    }

    // ---------------- cluster block ----------------
    if (tid == 0) { s_cnt = 0; s_qn = 0; }
    __syncthreads();

    // Barrier-free compaction: 16 chunks, atomic cursors, no per-chunk sync.
#pragma unroll
    for (int t = 0; t < NCHUNK; t++) {
        const int n = t * 256 + tid;
        if (lab[n] == c) {
            int p = atomicAdd(&s_cnt, 1);
            if (p < CAP) {
                const float* xv = xb + (size_t)n * 3;
                sx[p] = make_float4(xv[0], xv[1], xv[2], 0.f);
            }
            if (n < KOUT) {
                int qp = atomicAdd(&s_qn, 1);
                sq[qp] = n;
            }
        }
    }
    __syncthreads();

    const int cnt = min(s_cnt, CAP);
    const int qn  = s_qn;
    if (qn == 0) return;

    // Per-block constant weights (broadcast loads, L1-hot)
    const float scale = 0.57735026919f;  // 1/sqrt(3)
    float wq[9], bq3[3], wk[9], bk3[3], wv[9], bv3[3], wo[9], bo3[3];
#pragma unroll
    for (int i = 0; i < 9; i++) {
        wq[i] = __ldg(Wq + i); wk[i] = __ldg(Wk + i);
        wv[i] = __ldg(Wv + i); wo[i] = __ldg(Wo + i);
    }
#pragma unroll
    for (int i = 0; i < 3; i++) {
        bq3[i] = __ldg(bq + i); bk3[i] = __ldg(bk + i);
        bv3[i] = __ldg(bv + i); bo3[i] = __ldg(bo + i);
    }
    const float b20 = __ldg(b2 + 0), b21 = __ldg(b2 + 1), b22 = __ldg(b2 + 2);

    // One warp per query
    for (int qq = warp; qq < qn; qq += 8) {
        const int n = sq[qq];
        const float* xv = xb + (size_t)n * 3;
        float x0 = xv[0], x1 = xv[1], x2 = xv[2];
        // q = (Wq x + bq) * scale
        float q0 = fmaf(wq[0], x0, fmaf(wq[1], x1, fmaf(wq[2], x2, bq3[0]))) * scale;
        float q1 = fmaf(wq[3], x0, fmaf(wq[4], x1, fmaf(wq[5], x2, bq3[1]))) * scale;
        float q2 = fmaf(wq[6], x0, fmaf(wq[7], x1, fmaf(wq[8], x2, bq3[2]))) * scale;
        // score(x_m) = (Wk^T q)·x_m + q·bk
        float qk0 = fmaf(wk[0], q0, fmaf(wk[3], q1, wk[6] * q2));
        float qk1 = fmaf(wk[1], q0, fmaf(wk[4], q1, wk[7] * q2));
        float qk2 = fmaf(wk[2], q0, fmaf(wk[5], q1, wk[8] * q2));
        float qb  = fmaf(bk3[0], q0, fmaf(bk3[1], q1, bk3[2] * q2));

        // plain-exp softmax over member x (scores O(few): fp32 exp safe)
        float sm = 0.f, a0 = 0.f, a1 = 0.f, a2 = 0.f;
        for (int i = lane; i < cnt; i += 32) {
            float4 xm = sx[i];
            float s = fmaf(qk0, xm.x, fmaf(qk1, xm.y, fmaf(qk2, xm.z, qb)));
            float e = __expf(s);
            sm += e;
            a0 = fmaf(e, xm.x, a0);
            a1 = fmaf(e, xm.y, a1);
            a2 = fmaf(e, xm.z, a2);
        }
#pragma unroll
        for (int off = 16; off; off >>= 1) {
            sm += __shfl_down_sync(0xffffffffu, sm, off);
            a0 += __shfl_down_sync(0xffffffffu, a0, off);
            a1 += __shfl_down_sync(0xffffffffu, a1, off);
            a2 += __shfl_down_sync(0xffffffffu, a2, off);
        }
        sm = __shfl_sync(0xffffffffu, sm, 0);
        a0 = __shfl_sync(0xffffffffu, a0, 0);
        a1 = __shfl_sync(0xffffffffu, a1, 0);
        a2 = __shfl_sync(0xffffffffu, a2, 0);
        float inv = 1.f / sm;                 // sm > 0: query is its own member
        float m0 = a0 * inv, m1 = a1 * inv, m2 = a2 * inv;   // weighted mean x

        // ctx = Wv·m + bv  (linearity of v-projection over the softmax average)
        float c0 = fmaf(wv[0], m0, fmaf(wv[1], m1, fmaf(wv[2], m2, bv3[0])));
        float c1 = fmaf(wv[3], m0, fmaf(wv[4], m1, fmaf(wv[5], m2, bv3[1])));
        float c2 = fmaf(wv[6], m0, fmaf(wv[7], m1, fmaf(wv[8], m2, bv3[2])));

        // out_proj
        float o0 = fmaf(wo[0], c0, fmaf(wo[1], c1, fmaf(wo[2], c2, bo3[0])));
        float o1 = fmaf(wo[3], c0, fmaf(wo[4], c1, fmaf(wo[5], c2, bo3[1])));
        float o2 = fmaf(wo[6], c0, fmaf(wo[7], c1, fmaf(wo[8], c2, bo3[2])));

        // MLP 3->256->3: 8 hidden units per lane, smem weights
        float y0 = 0.f, y1 = 0.f, y2 = 0.f;
#pragma unroll
        for (int t = 0; t < HH / 32; t++) {
            int j = lane + t * 32;
            float h = fmaf(sW1[j*3+0], o0, fmaf(sW1[j*3+1], o1, fmaf(sW1[j*3+2], o2, sb1[j])));
            h = fmaxf(h, 0.f);
            y0 = fmaf(sW2[j], h, y0);
            y1 = fmaf(sW2[HH + j], h, y1);
            y2 = fmaf(sW2[2*HH + j], h, y2);
        }
#pragma unroll
        for (int off = 16; off; off >>= 1) {
            y0 += __shfl_down_sync(0xffffffffu, y0, off);
            y1 += __shfl_down_sync(0xffffffffu, y1, off);
            y2 += __shfl_down_sync(0xffffffffu, y2, off);
        }
        if (lane == 0) {
            float* op = out + (size_t)(b * KOUT + n) * 3;
            op[0] = y0 + b20;
            op[1] = y1 + b21;
            op[2] = y2 + b22;
        }
    }
}

// ---------------------------------------------------------------------------
extern "C" void kernel_launch(void* const* d_in, const int* in_sizes, int n_in,
                              void* d_out, int out_size)
{
    const float* x      = (const float*)d_in[0];
    const int*   labels = (const int*)  d_in[1];
    const float* Wq = (const float*)d_in[2];
    const float* bq = (const float*)d_in[3];
    const float* Wk = (const float*)d_in[4];
    const float* bk = (const float*)d_in[5];
    const float* Wv = (const float*)d_in[6];
    const float* bv = (const float*)d_in[7];
    const float* Wo = (const float*)d_in[8];
    const float* bo = (const float*)d_in[9];
    const float* W1 = (const float*)d_in[10];
    const float* b1 = (const float*)d_in[11];
    const float* W2 = (const float*)d_in[12];
    const float* b2 = (const float*)d_in[13];
    float* out = (float*)d_out;

    fused_kernel<<<BATCH * 64, 256>>>(x, labels, Wq, bq, Wk, bk, Wv, bv,
                                      Wo, bo, W1, b1, W2, b2, out);
}

// round 8
// speedup vs baseline: 1.7775x; 1.2246x over previous
#include <cuda_runtime.h>
#include <math.h>

#define BATCH 8
#define NPTS  4096
#define HH    256
#define KOUT  1024
#define NC    63
#define CAP   512           // smem member capacity (E[cnt]=64, sigma=8 -> 40+ sigma margin)

// ---------------------------------------------------------------------------
// Single kernel. Block (b,c): c in [0,63) = cluster block, c==63 = noise rows.
// Barrier-free atomic compaction of member x into smem; per-block pre-folded
// weights:
//   score(x_m) = qk·x_m + qb,   qk = M·x_q + u,  qb = wb·x_q + s0
//   o          = N·mean + p     (Wv, Wo folded; k/v/ctx never materialized)
// ---------------------------------------------------------------------------
__global__ __launch_bounds__(256, 4)
void fused_kernel(const float* __restrict__ x,
                  const int*   __restrict__ labels,
                  const float* __restrict__ Wq, const float* __restrict__ bq,
                  const float* __restrict__ Wk, const float* __restrict__ bk,
                  const float* __restrict__ Wv, const float* __restrict__ bv,
                  const float* __restrict__ Wo, const float* __restrict__ bo,
                  const float* __restrict__ W1, const float* __restrict__ b1,
                  const float* __restrict__ W2, const float* __restrict__ b2,
                  float* __restrict__ out)
{
    __shared__ float4 sx[CAP];            // member x (w unused)
    __shared__ int    sq[CAP];            // member query rows (n < KOUT)
    __shared__ float  sW1[HH * 3], sW2[3 * HH], sb1[HH];
    __shared__ float  sM[9], su[3], swb[3], sNw[9], sp[3], s_s0;
    __shared__ int    s_cnt, s_qn;
    __shared__ float  s_y3[3];

    const int tid  = threadIdx.x;
    const int warp = tid >> 5;
    const int lane = tid & 31;
    const int b    = blockIdx.x >> 6;
    const int c    = blockIdx.x & 63;

    const int*   lab = labels + b * NPTS;
    const float* xb  = x + (size_t)b * NPTS * 3;

    // Stage MLP weights (used by every query in this block)
    for (int i = tid; i < HH * 3; i += 256) { sW1[i] = W1[i]; sW2[i] = W2[i]; }
    for (int i = tid; i < HH; i += 256) sb1[i] = b1[i];

    // ---------------- noise block: constant output for label==-1 rows --------
    if (c == NC) {
        __syncthreads();
        if (warp == 0) {
            float o0 = __ldg(bo + 0), o1 = __ldg(bo + 1), o2 = __ldg(bo + 2);
            float y0 = 0.f, y1 = 0.f, y2 = 0.f;
#pragma unroll
            for (int t = 0; t < HH / 32; t++) {
                int j = lane + t * 32;
                float h = fmaf(sW1[j*3+0], o0, fmaf(sW1[j*3+1], o1, fmaf(sW1[j*3+2], o2, sb1[j])));
                h = fmaxf(h, 0.f);
                y0 = fmaf(sW2[j], h, y0);
                y1 = fmaf(sW2[HH + j], h, y1);
                y2 = fmaf(sW2[2*HH + j], h, y2);
            }
#pragma unroll
            for (int off = 16; off; off >>= 1) {
                y0 += __shfl_down_sync(0xffffffffu, y0, off);
                y1 += __shfl_down_sync(0xffffffffu, y1, off);
                y2 += __shfl_down_sync(0xffffffffu, y2, off);
            }
            if (lane == 0) {
                s_y3[0] = y0 + __ldg(b2 + 0);
                s_y3[1] = y1 + __ldg(b2 + 1);
                s_y3[2] = y2 + __ldg(b2 + 2);
            }
        }
        __syncthreads();
        float y0 = s_y3[0], y1 = s_y3[1], y2 = s_y3[2];
        // vectorized: 4 labels per thread, all n < KOUT
        const int4 L = reinterpret_cast<const int4*>(lab)[tid];
        const int n0 = tid * 4;
        if (L.x == -1) { float* op = out + (size_t)(b*KOUT + n0    )*3; op[0]=y0; op[1]=y1; op[2]=y2; }
        if (L.y == -1) { float* op = out + (size_t)(b*KOUT + n0 + 1)*3; op[0]=y0; op[1]=y1; op[2]=y2; }
        if (L.z == -1) { float* op = out + (size_t)(b*KOUT + n0 + 2)*3; op[0]=y0; op[1]=y1; op[2]=y2; }
        if (L.w == -1) { float* op = out + (size_t)(b*KOUT + n0 + 3)*3; op[0]=y0; op[1]=y1; op[2]=y2; }
        return;
    }

    // ---------------- cluster block ----------------
    if (tid == 0) { s_cnt = 0; s_qn = 0; }

    // Thread 255 pre-folds the linear algebra (hidden under other threads' work)
    if (tid == 255) {
        const float scale = 0.57735026919f;   // 1/sqrt(3)
        float wq[9], wk[9], wv[9], wo[9], bq3[3], bk3[3], bv3[3], bo3[3];
#pragma unroll
        for (int i = 0; i < 9; i++) {
            wq[i] = __ldg(Wq + i); wk[i] = __ldg(Wk + i);
            wv[i] = __ldg(Wv + i); wo[i] = __ldg(Wo + i);
        }
#pragma unroll
        for (int i = 0; i < 3; i++) {
            bq3[i] = __ldg(bq + i); bk3[i] = __ldg(bk + i);
            bv3[i] = __ldg(bv + i); bo3[i] = __ldg(bo + i);
        }
        // qk_c = sum_d M[c*3+d] xq_d + u[c];  M[c][d] = scale*sum_r Wq[r*3+d]*Wk[r*3+c]
#pragma unroll
        for (int cc = 0; cc < 3; cc++) {
#pragma unroll
            for (int d = 0; d < 3; d++)
                sM[cc*3+d] = scale * (wq[d]*wk[cc] + wq[3+d]*wk[3+cc] + wq[6+d]*wk[6+cc]);
            su[cc]  = scale * (bq3[0]*wk[cc] + bq3[1]*wk[3+cc] + bq3[2]*wk[6+cc]);
            swb[cc] = scale * (bk3[0]*wq[cc] + bk3[1]*wq[3+cc] + bk3[2]*wq[6+cc]);
        }
        s_s0 = scale * (bk3[0]*bq3[0] + bk3[1]*bq3[1] + bk3[2]*bq3[2]);
        // o_r = sum_c N[r*3+c] m_c + p[r];  N = Wo*Wv, p = Wo*bv + bo
#pragma unroll
        for (int r = 0; r < 3; r++) {
#pragma unroll
            for (int cc = 0; cc < 3; cc++)
                sNw[r*3+cc] = wo[r*3+0]*wv[cc] + wo[r*3+1]*wv[3+cc] + wo[r*3+2]*wv[6+cc];
            sp[r] = wo[r*3+0]*bv3[0] + wo[r*3+1]*bv3[1] + wo[r*3+2]*bv3[2] + bo3[r];
        }
    }
    __syncthreads();

    // Barrier-free compaction: 4 int4 label loads per thread, atomic cursors.
    const int4* lab4 = reinterpret_cast<const int4*>(lab);
#pragma unroll
    for (int t = 0; t < 4; t++) {
        const int  i = t * 256 + tid;
        const int4 L = lab4[i];
        const int  n0 = i * 4;
#pragma unroll
        for (int j = 0; j < 4; j++) {
            const int lj = (j == 0) ? L.x : (j == 1) ? L.y : (j == 2) ? L.z : L.w;
            if (lj == c) {
                const int n = n0 + j;
                int p = atomicAdd(&s_cnt, 1);
                if (p < CAP) {
                    const float* xv = xb + (size_t)n * 3;
                    sx[p] = make_float4(xv[0], xv[1], xv[2], 0.f);
                }
                if (t == 0) {                      // t==0 <=> n < KOUT
                    int qp = atomicAdd(&s_qn, 1);
                    sq[qp] = n;
                }
            }
        }
    }
    __syncthreads();

    const int cnt = min(s_cnt, CAP);
    const int qn  = s_qn;
    if (qn == 0) return;

    const float b20 = __ldg(b2 + 0), b21 = __ldg(b2 + 1), b22 = __ldg(b2 + 2);

    // One warp per query
    for (int qq = warp; qq < qn; qq += 8) {
        const int n = sq[qq];
        const float* xv = xb + (size_t)n * 3;
        const float x0 = xv[0], x1 = xv[1], x2 = xv[2];
        const float qk0 = fmaf(sM[0], x0, fmaf(sM[1], x1, fmaf(sM[2], x2, su[0])));
        const float qk1 = fmaf(sM[3], x0, fmaf(sM[4], x1, fmaf(sM[5], x2, su[1])));
        const float qk2 = fmaf(sM[6], x0, fmaf(sM[7], x1, fmaf(sM[8], x2, su[2])));
        const float qb  = fmaf(swb[0], x0, fmaf(swb[1], x1, fmaf(swb[2], x2, s_s0)));

        // plain-exp softmax over member x (scores O(few): fp32 exp safe)
        float sm = 0.f, a0 = 0.f, a1 = 0.f, a2 = 0.f;
        for (int i = lane; i < cnt; i += 32) {
            float4 xm = sx[i];
            float s = fmaf(qk0, xm.x, fmaf(qk1, xm.y, fmaf(qk2, xm.z, qb)));
            float e = __expf(s);
            sm += e;
            a0 = fmaf(e, xm.x, a0);
            a1 = fmaf(e, xm.y, a1);
            a2 = fmaf(e, xm.z, a2);
        }
#pragma unroll
        for (int off = 16; off; off >>= 1) {
            sm += __shfl_down_sync(0xffffffffu, sm, off);
            a0 += __shfl_down_sync(0xffffffffu, a0, off);
            a1 += __shfl_down_sync(0xffffffffu, a1, off);
            a2 += __shfl_down_sync(0xffffffffu, a2, off);
        }
        sm = __shfl_sync(0xffffffffu, sm, 0);
        a0 = __shfl_sync(0xffffffffu, a0, 0);
        a1 = __shfl_sync(0xffffffffu, a1, 0);
        a2 = __shfl_sync(0xffffffffu, a2, 0);
        const float inv = 1.f / sm;             // sm > 0: query is its own member
        const float m0 = a0 * inv, m1 = a1 * inv, m2 = a2 * inv;

        // o = N*mean + p  (Wv and Wo folded)
        const float o0 = fmaf(sNw[0], m0, fmaf(sNw[1], m1, fmaf(sNw[2], m2, sp[0])));
        const float o1 = fmaf(sNw[3], m0, fmaf(sNw[4], m1, fmaf(sNw[5], m2, sp[1])));
        const float o2 = fmaf(sNw[6], m0, fmaf(sNw[7], m1, fmaf(sNw[8], m2, sp[2])));

        // MLP 3->256->3: 8 hidden units per lane, smem weights
        float y0 = 0.f, y1 = 0.f, y2 = 0.f;
#pragma unroll
        for (int t = 0; t < HH / 32; t++) {
            int j = lane + t * 32;
            float h = fmaf(sW1[j*3+0], o0, fmaf(sW1[j*3+1], o1, fmaf(sW1[j*3+2], o2, sb1[j])));
            h = fmaxf(h, 0.f);
            y0 = fmaf(sW2[j], h, y0);
            y1 = fmaf(sW2[HH + j], h, y1);
            y2 = fmaf(sW2[2*HH + j], h, y2);
        }
#pragma unroll
        for (int off = 16; off; off >>= 1) {
            y0 += __shfl_down_sync(0xffffffffu, y0, off);
            y1 += __shfl_down_sync(0xffffffffu, y1, off);
            y2 += __shfl_down_sync(0xffffffffu, y2, off);
        }
        if (lane == 0) {
            float* op = out + (size_t)(b * KOUT + n) * 3;
            op[0] = y0 + b20;
            op[1] = y1 + b21;
            op[2] = y2 + b22;
        }
    }
}

// ---------------------------------------------------------------------------
extern "C" void kernel_launch(void* const* d_in, const int* in_sizes, int n_in,
                              void* d_out, int out_size)
{
    const float* x      = (const float*)d_in[0];
    const int*   labels = (const int*)  d_in[1];
    const float* Wq = (const float*)d_in[2];
    const float* bq = (const float*)d_in[3];
    const float* Wk = (const float*)d_in[4];
    const float* bk = (const float*)d_in[5];
    const float* Wv = (const float*)d_in[6];
    const float* bv = (const float*)d_in[7];
    const float* Wo = (const float*)d_in[8];
    const float* bo = (const float*)d_in[9];
    const float* W1 = (const float*)d_in[10];
    const float* b1 = (const float*)d_in[11];
    const float* W2 = (const float*)d_in[12];
    const float* b2 = (const float*)d_in[13];
    float* out = (float*)d_out;

    fused_kernel<<<BATCH * 64, 256>>>(x, labels, Wq, bq, Wk, bk, Wv, bv,
                                      Wo, bo, W1, b1, W2, b2, out);
}

// round 10
// speedup vs baseline: 1.7813x; 1.0021x over previous
#include <cuda_runtime.h>
#include <math.h>

#define BATCH 8
#define NPTS  4096
#define HH    256
#define KOUT  1024
#define NC    63
#define CAP   512           // smem member capacity (E[cnt]=64 -> 40+ sigma margin)

// ---------------------------------------------------------------------------
// Single kernel. Block (b,c): c in [0,63) = cluster block, c==63 = noise rows.
// Barrier-free atomic compaction of member x into smem; per-block pre-folded
// weights (computed in parallel by 28 threads):
//   score(x_m) = qk·x_m + qb,   qk = M·x_q + u,  qb = wb·x_q + s0
//   o          = N·mean + p     (k/v/ctx never materialized)
// Warps process 2 queries at once, sharing every sx/weight smem load.
// ---------------------------------------------------------------------------
__global__ __launch_bounds__(256, 4)
void fused_kernel(const float* __restrict__ x,
                  const int*   __restrict__ labels,
                  const float* __restrict__ Wq, const float* __restrict__ bq,
                  const float* __restrict__ Wk, const float* __restrict__ bk,
                  const float* __restrict__ Wv, const float* __restrict__ bv,
                  const float* __restrict__ Wo, const float* __restrict__ bo,
                  const float* __restrict__ W1, const float* __restrict__ b1,
                  const float* __restrict__ W2, const float* __restrict__ b2,
                  float* __restrict__ out)
{
    __shared__ float4 sx[CAP];            // member x (w unused)
    __shared__ int    sq[CAP];            // (smem pos << 16) | query row n
    __shared__ float  sW1[HH * 3], sW2[3 * HH], sb1[HH];
    __shared__ float  sM[9], su[3], swb[3], sNw[9], sp[3], s_s0;
    __shared__ int    s_cnt, s_qn;
    __shared__ float  s_y3[3];

    const int tid  = threadIdx.x;
    const int warp = tid >> 5;
    const int lane = tid & 31;
    const int b    = blockIdx.x >> 6;
    const int c    = blockIdx.x & 63;

    const int*   lab = labels + b * NPTS;
    const float* xb  = x + (size_t)b * NPTS * 3;

    // Stage MLP weights (independent of everything; overlaps with init)
    for (int i = tid; i < HH * 3; i += 256) { sW1[i] = W1[i]; sW2[i] = W2[i]; }
    for (int i = tid; i < HH; i += 256) sb1[i] = b1[i];

    // ---------------- noise block: constant output for label==-1 rows --------
    if (c == NC) {
        __syncthreads();
        if (warp == 0) {
            float o0 = __ldg(bo + 0), o1 = __ldg(bo + 1), o2 = __ldg(bo + 2);
            float y0 = 0.f, y1 = 0.f, y2 = 0.f;
#pragma unroll
            for (int t = 0; t < HH / 32; t++) {
                int j = lane + t * 32;
                float h = fmaf(sW1[j*3+0], o0, fmaf(sW1[j*3+1], o1, fmaf(sW1[j*3+2], o2, sb1[j])));
                h = fmaxf(h, 0.f);
                y0 = fmaf(sW2[j], h, y0);
                y1 = fmaf(sW2[HH + j], h, y1);
                y2 = fmaf(sW2[2*HH + j], h, y2);
            }
#pragma unroll
            for (int off = 16; off; off >>= 1) {
                y0 += __shfl_down_sync(0xffffffffu, y0, off);
                y1 += __shfl_down_sync(0xffffffffu, y1, off);
                y2 += __shfl_down_sync(0xffffffffu, y2, off);
            }
            if (lane == 0) {
                s_y3[0] = y0 + __ldg(b2 + 0);
                s_y3[1] = y1 + __ldg(b2 + 1);
                s_y3[2] = y2 + __ldg(b2 + 2);
            }
        }
        __syncthreads();
        float y0 = s_y3[0], y1 = s_y3[1], y2 = s_y3[2];
        const int4 L = reinterpret_cast<const int4*>(lab)[tid];
        const int n0 = tid * 4;
        if (L.x == -1) { float* op = out + (size_t)(b*KOUT + n0    )*3; op[0]=y0; op[1]=y1; op[2]=y2; }
        if (L.y == -1) { float* op = out + (size_t)(b*KOUT + n0 + 1)*3; op[0]=y0; op[1]=y1; op[2]=y2; }
        if (L.z == -1) { float* op = out + (size_t)(b*KOUT + n0 + 2)*3; op[0]=y0; op[1]=y1; op[2]=y2; }
        if (L.w == -1) { float* op = out + (size_t)(b*KOUT + n0 + 3)*3; op[0]=y0; op[1]=y1; op[2]=y2; }
        return;
    }

    // ---------------- cluster block ----------------
    if (tid == 0) { s_cnt = 0; s_qn = 0; }
    __syncthreads();

    // Barrier-free compaction: 4 int4 label loads per thread, atomic cursors.
    const int4* lab4 = reinterpret_cast<const int4*>(lab);
#pragma unroll
    for (int t = 0; t < 4; t++) {
        const int  i = t * 256 + tid;
        const int4 L = lab4[i];
        const int  n0 = i * 4;
#pragma unroll
        for (int j = 0; j < 4; j++) {
            const int lj = (j == 0) ? L.x : (j == 1) ? L.y : (j == 2) ? L.z : L.w;
            if (lj == c) {
                const int n = n0 + j;
                int p = atomicAdd(&s_cnt, 1);
                if (p < CAP) {
                    const float* xv = xb + (size_t)n * 3;
                    sx[p] = make_float4(xv[0], xv[1], xv[2], 0.f);
                }
                if (t == 0) {                      // t==0 <=> n < KOUT
                    int qp = atomicAdd(&s_qn, 1);
                    sq[qp] = n | (p << 16);
                }
            }
        }
    }

    // Parallel prefold: 28 threads, one folded scalar each (after their scan,
    // loads overlap other threads' compaction latency).
    if (tid < 28) {
        const float scale = 0.57735026919f;   // 1/sqrt(3)
        const int i = tid;
        if (i < 9) {
            int cc = i / 3, d = i % 3;
            sM[i] = scale * (__ldg(Wq+d)  *__ldg(Wk+cc)
                           + __ldg(Wq+3+d)*__ldg(Wk+3+cc)
                           + __ldg(Wq+6+d)*__ldg(Wk+6+cc));
        } else if (i < 12) {
            int cc = i - 9;
            su[cc] = scale * (__ldg(bq+0)*__ldg(Wk+cc)
                            + __ldg(bq+1)*__ldg(Wk+3+cc)
                            + __ldg(bq+2)*__ldg(Wk+6+cc));
        } else if (i < 15) {
            int cc = i - 12;
            swb[cc] = scale * (__ldg(bk+0)*__ldg(Wq+cc)
                             + __ldg(bk+1)*__ldg(Wq+3+cc)
                             + __ldg(bk+2)*__ldg(Wq+6+cc));
        } else if (i == 15) {
            s_s0 = scale * (__ldg(bk+0)*__ldg(bq+0)
                          + __ldg(bk+1)*__ldg(bq+1)
                          + __ldg(bk+2)*__ldg(bq+2));
        } else if (i < 25) {
            int r = (i - 16) / 3, cc = (i - 16) % 3;
            sNw[i-16] = __ldg(Wo+r*3+0)*__ldg(Wv+cc)
                      + __ldg(Wo+r*3+1)*__ldg(Wv+3+cc)
                      + __ldg(Wo+r*3+2)*__ldg(Wv+6+cc);
        } else {
            int r = i - 25;
            sp[r] = __ldg(Wo+r*3+0)*__ldg(bv+0)
                  + __ldg(Wo+r*3+1)*__ldg(bv+1)
                  + __ldg(Wo+r*3+2)*__ldg(bv+2) + __ldg(bo+r);
        }
    }
    __syncthreads();

    const int cnt = min(s_cnt, CAP);
    const int qn  = s_qn;
    if (qn == 0) return;

    const float b20 = __ldg(b2 + 0), b21 = __ldg(b2 + 1), b22 = __ldg(b2 + 2);

    // Two queries per warp per round (ILP + shared smem loads)
    for (int qq = warp * 2; qq < qn; qq += 16) {
        const int  e0   = sq[qq];
        const bool has2 = (qq + 1) < qn;
        const int  e1   = has2 ? sq[qq + 1] : e0;
        const int  n0q  = e0 & 0xFFFF, p0 = e0 >> 16;
        const int  n1q  = e1 & 0xFFFF, p1 = e1 >> 16;

        float4 xqa, xqb;
        if (p0 < CAP) xqa = sx[p0];
        else { const float* xv = xb + (size_t)n0q * 3; xqa = make_float4(xv[0], xv[1], xv[2], 0.f); }
        if (p1 < CAP) xqb = sx[p1];
        else { const float* xv = xb + (size_t)n1q * 3; xqb = make_float4(xv[0], xv[1], xv[2], 0.f); }

        const float qkA0 = fmaf(sM[0], xqa.x, fmaf(sM[1], xqa.y, fmaf(sM[2], xqa.z, su[0])));
        const float qkA1 = fmaf(sM[3], xqa.x, fmaf(sM[4], xqa.y, fmaf(sM[5], xqa.z, su[1])));
        const float qkA2 = fmaf(sM[6], xqa.x, fmaf(sM[7], xqa.y, fmaf(sM[8], xqa.z, su[2])));
        const float qbA  = fmaf(swb[0], xqa.x, fmaf(swb[1], xqa.y, fmaf(swb[2], xqa.z, s_s0)));
        const float qkB0 = fmaf(sM[0], xqb.x, fmaf(sM[1], xqb.y, fmaf(sM[2], xqb.z, su[0])));
        const float qkB1 = fmaf(sM[3], xqb.x, fmaf(sM[4], xqb.y, fmaf(sM[5], xqb.z, su[1])));
        const float qkB2 = fmaf(sM[6], xqb.x, fmaf(sM[7], xqb.y, fmaf(sM[8], xqb.z, su[2])));
        const float qbB  = fmaf(swb[0], xqb.x, fmaf(swb[1], xqb.y, fmaf(swb[2], xqb.z, s_s0)));

        // dual plain-exp softmax; one sx load feeds both queries
        float smA = 0.f, aA0 = 0.f, aA1 = 0.f, aA2 = 0.f;
        float smB = 0.f, aB0 = 0.f, aB1 = 0.f, aB2 = 0.f;
        for (int i = lane; i < cnt; i += 32) {
            const float4 xm = sx[i];
            const float sA = fmaf(qkA0, xm.x, fmaf(qkA1, xm.y, fmaf(qkA2, xm.z, qbA)));
            const float sB = fmaf(qkB0, xm.x, fmaf(qkB1, xm.y, fmaf(qkB2, xm.z, qbB)));
            const float eA = __expf(sA);
            const float eB = __expf(sB);
            smA += eA; smB += eB;
            aA0 = fmaf(eA, xm.x, aA0); aB0 = fmaf(eB, xm.x, aB0);
            aA1 = fmaf(eA, xm.y, aA1); aB1 = fmaf(eB, xm.y, aB1);
            aA2 = fmaf(eA, xm.z, aA2); aB2 = fmaf(eB, xm.z, aB2);
        }
#pragma unroll
        for (int off = 16; off; off >>= 1) {
            smA += __shfl_down_sync(0xffffffffu, smA, off);
            aA0 += __shfl_down_sync(0xffffffffu, aA0, off);
            aA1 += __shfl_down_sync(0xffffffffu, aA1, off);
            aA2 += __shfl_down_sync(0xffffffffu, aA2, off);
            smB += __shfl_down_sync(0xffffffffu, smB, off);
            aB0 += __shfl_down_sync(0xffffffffu, aB0, off);
            aB1 += __shfl_down_sync(0xffffffffu, aB1, off);
            aB2 += __shfl_down_sync(0xffffffffu, aB2, off);
        }
        smA = __shfl_sync(0xffffffffu, smA, 0);
        aA0 = __shfl_sync(0xffffffffu, aA0, 0);
        aA1 = __shfl_sync(0xffffffffu, aA1, 0);
        aA2 = __shfl_sync(0xffffffffu, aA2, 0);
        smB = __shfl_sync(0xffffffffu, smB, 0);
        aB0 = __shfl_sync(0xffffffffu, aB0, 0);
        aB1 = __shfl_sync(0xffffffffu, aB1, 0);
        aB2 = __shfl_sync(0xffffffffu, aB2, 0);

        const float invA = 1.f / smA, invB = 1.f / smB;
        const float mA0 = aA0 * invA, mA1 = aA1 * invA, mA2 = aA2 * invA;
        const float mB0 = aB0 * invB, mB1 = aB1 * invB, mB2 = aB2 * invB;

        const float oA0 = fmaf(sNw[0], mA0, fmaf(sNw[1], mA1, fmaf(sNw[2], mA2, sp[0])));
        const float oA1 = fmaf(sNw[3], mA0, fmaf(sNw[4], mA1, fmaf(sNw[5], mA2, sp[1])));
        const float oA2 = fmaf(sNw[6], mA0, fmaf(sNw[7], mA1, fmaf(sNw[8], mA2, sp[2])));
        const float oB0 = fmaf(sNw[0], mB0, fmaf(sNw[1], mB1, fmaf(sNw[2], mB2, sp[0])));
        const float oB1 = fmaf(sNw[3], mB0, fmaf(sNw[4], mB1, fmaf(sNw[5], mB2, sp[1])));
        const float oB2 = fmaf(sNw[6], mB0, fmaf(sNw[7], mB1, fmaf(sNw[8], mB2, sp[2])));

        // dual MLP: weight loads shared between the two queries
        float yA0 = 0.f, yA1 = 0.f, yA2 = 0.f;
        float yB0 = 0.f, yB1 = 0.f, yB2 = 0.f;
#pragma unroll
        for (int t = 0; t < HH / 32; t++) {
            const int j = lane + t * 32;
            const float w0 = sW1[j*3+0], w1 = sW1[j*3+1], w2 = sW1[j*3+2], bb = sb1[j];
            float hA = fmaf(w0, oA0, fmaf(w1, oA1, fmaf(w2, oA2, bb)));
            float hB = fmaf(w0, oB0, fmaf(w1, oB1, fmaf(w2, oB2, bb)));
            hA = fmaxf(hA, 0.f); hB = fmaxf(hB, 0.f);
            const float u0 = sW2[j], u1 = sW2[HH + j], u2 = sW2[2*HH + j];
            yA0 = fmaf(u0, hA, yA0); yB0 = fmaf(u0, hB, yB0);
            yA1 = fmaf(u1, hA, yA1); yB1 = fmaf(u1, hB, yB1);
            yA2 = fmaf(u2, hA, yA2); yB2 = fmaf(u2, hB, yB2);
        }
#pragma unroll
        for (int off = 16; off; off >>= 1) {
            yA0 += __shfl_down_sync(0xffffffffu, yA0, off);
            yA1 += __shfl_down_sync(0xffffffffu, yA1, off);
            yA2 += __shfl_down_sync(0xffffffffu, yA2, off);
            yB0 += __shfl_down_sync(0xffffffffu, yB0, off);
            yB1 += __shfl_down_sync(0xffffffffu, yB1, off);
            yB2 += __shfl_down_sync(0xffffffffu, yB2, off);
        }
        if (lane == 0) {
            float* op = out + (size_t)(b * KOUT + n0q) * 3;
            op[0] = yA0 + b20; op[1] = yA1 + b21; op[2] = yA2 + b22;
            if (has2) {
                float* oq = out + (size_t)(b * KOUT + n1q) * 3;
                oq[0] = yB0 + b20; oq[1] = yB1 + b21; oq[2] = yB2 + b22;
            }
        }
    }
}

// ---------------------------------------------------------------------------
extern "C" void kernel_launch(void* const* d_in, const int* in_sizes, int n_in,
                              void* d_out, int out_size)
{
    const float* x      = (const float*)d_in[0];
    const int*   labels = (const int*)  d_in[1];
    const float* Wq = (const float*)d_in[2];
    const float* bq = (const float*)d_in[3];
    const float* Wk = (const float*)d_in[4];
    const float* bk = (const float*)d_in[5];
    const float* Wv = (const float*)d_in[6];
    const float* bv = (const float*)d_in[7];
    const float* Wo = (const float*)d_in[8];
    const float* bo = (const float*)d_in[9];
    const float* W1 = (const float*)d_in[10];
    const float* b1 = (const float*)d_in[11];
    const float* W2 = (const float*)d_in[12];
    const float* b2 = (const float*)d_in[13];
    float* out = (float*)d_out;

    fused_kernel<<<BATCH * 64, 256>>>(x, labels, Wq, bq, Wk, bk, Wv, bv,
                                      Wo, bo, W1, b1, W2, b2, out);
}

// round 11
// speedup vs baseline: 2.1028x; 1.1805x over previous
#include <cuda_runtime.h>
#include <math.h>

#define BATCH 8
#define NPTS  4096
#define HH    256
#define KOUT  1024
#define NC    63
#define CAP   512           // smem member capacity (E[cnt]=64 -> 40+ sigma margin)

// ---------------------------------------------------------------------------
// Single kernel. Block (b,c): c in [0,63) = cluster block, c==63 = noise rows.
// Barrier-free atomic compaction of member x into smem; per-block pre-folded
// weights:
//   score(x_m) = qk·x_m + qb,   qk = M·x_q + u,  qb = wb·x_q + s0
//   o          = N·mean + p     (k/v/ctx never materialized)
// MLP weights packed as float4 in smem: inner loop = 2 LDS.128 + FMAs only.
// ---------------------------------------------------------------------------
__global__ __launch_bounds__(256, 4)
void fused_kernel(const float* __restrict__ x,
                  const int*   __restrict__ labels,
                  const float* __restrict__ Wq, const float* __restrict__ bq,
                  const float* __restrict__ Wk, const float* __restrict__ bk,
                  const float* __restrict__ Wv, const float* __restrict__ bv,
                  const float* __restrict__ Wo, const float* __restrict__ bo,
                  const float* __restrict__ W1, const float* __restrict__ b1,
                  const float* __restrict__ W2, const float* __restrict__ b2,
                  float* __restrict__ out)
{
    __shared__ float4 sx[CAP];            // member x (w unused)
    __shared__ int    sq[CAP];            // (smem pos << 16) | query row n
    __shared__ float4 sW1p[HH];           // (W1[3j], W1[3j+1], W1[3j+2], b1[j])
    __shared__ float4 sW2p[HH];           // (W2[j], W2[HH+j], W2[2HH+j], 0)
    __shared__ float  sM[9], su[3], swb[3], sNw[9], sp[3], s_s0;
    __shared__ int    s_cnt, s_qn;
    __shared__ float  s_y3[3];

    const int tid  = threadIdx.x;
    const int warp = tid >> 5;
    const int lane = tid & 31;
    const int b    = blockIdx.x >> 6;
    const int c    = blockIdx.x & 63;

    const int*   lab = labels + b * NPTS;
    const float* xb  = x + (size_t)b * NPTS * 3;

    // Stage MLP weights packed (one j per thread; 256 == HH)
    {
        const int j = tid;
        sW1p[j] = make_float4(W1[3*j], W1[3*j+1], W1[3*j+2], b1[j]);
        sW2p[j] = make_float4(W2[j], W2[HH + j], W2[2*HH + j], 0.f);
    }

    // ---------------- noise block: constant output for label==-1 rows --------
    if (c == NC) {
        __syncthreads();
        if (warp == 0) {
            float o0 = __ldg(bo + 0), o1 = __ldg(bo + 1), o2 = __ldg(bo + 2);
            float y0 = 0.f, y1 = 0.f, y2 = 0.f;
#pragma unroll
            for (int t = 0; t < HH / 32; t++) {
                int j = lane + t * 32;
                float4 w = sW1p[j];
                float h = fmaf(w.x, o0, fmaf(w.y, o1, fmaf(w.z, o2, w.w)));
                h = fmaxf(h, 0.f);
                float4 u = sW2p[j];
                y0 = fmaf(u.x, h, y0);
                y1 = fmaf(u.y, h, y1);
                y2 = fmaf(u.z, h, y2);
            }
#pragma unroll
            for (int off = 16; off; off >>= 1) {
                y0 += __shfl_down_sync(0xffffffffu, y0, off);
                y1 += __shfl_down_sync(0xffffffffu, y1, off);
                y2 += __shfl_down_sync(0xffffffffu, y2, off);
            }
            if (lane == 0) {
                s_y3[0] = y0 + __ldg(b2 + 0);
                s_y3[1] = y1 + __ldg(b2 + 1);
                s_y3[2] = y2 + __ldg(b2 + 2);
            }
        }
        __syncthreads();
        float y0 = s_y3[0], y1 = s_y3[1], y2 = s_y3[2];
        const int4 L = reinterpret_cast<const int4*>(lab)[tid];
        const int n0 = tid * 4;
        if (L.x == -1) { float* op = out + (size_t)(b*KOUT + n0    )*3; op[0]=y0; op[1]=y1; op[2]=y2; }
        if (L.y == -1) { float* op = out + (size_t)(b*KOUT + n0 + 1)*3; op[0]=y0; op[1]=y1; op[2]=y2; }
        if (L.z == -1) { float* op = out + (size_t)(b*KOUT + n0 + 2)*3; op[0]=y0; op[1]=y1; op[2]=y2; }
        if (L.w == -1) { float* op = out + (size_t)(b*KOUT + n0 + 3)*3; op[0]=y0; op[1]=y1; op[2]=y2; }
        return;
    }

    // ---------------- cluster block ----------------
    if (tid == 0) { s_cnt = 0; s_qn = 0; }
    __syncthreads();

    // Barrier-free compaction: 4 int4 label loads per thread, atomic cursors.
    const int4* lab4 = reinterpret_cast<const int4*>(lab);
#pragma unroll
    for (int t = 0; t < 4; t++) {
        const int  i = t * 256 + tid;
        const int4 L = lab4[i];
        const int  n0 = i * 4;
#pragma unroll
        for (int j = 0; j < 4; j++) {
            const int lj = (j == 0) ? L.x : (j == 1) ? L.y : (j == 2) ? L.z : L.w;
            if (lj == c) {
                const int n = n0 + j;
                int p = atomicAdd(&s_cnt, 1);
                if (p < CAP) {
                    const float* xv = xb + (size_t)n * 3;
                    sx[p] = make_float4(xv[0], xv[1], xv[2], 0.f);
                }
                if (t == 0) {                      // t==0 <=> n < KOUT
                    int qp = atomicAdd(&s_qn, 1);
                    sq[qp] = n | (p << 16);
                }
            }
        }
    }

    // Parallel prefold: 28 threads, one folded scalar each.
    if (tid < 28) {
        const float scale = 0.57735026919f;   // 1/sqrt(3)
        const int i = tid;
        if (i < 9) {
            int cc = i / 3, d = i % 3;
            sM[i] = scale * (__ldg(Wq+d)  *__ldg(Wk+cc)
                           + __ldg(Wq+3+d)*__ldg(Wk+3+cc)
                           + __ldg(Wq+6+d)*__ldg(Wk+6+cc));
        } else if (i < 12) {
            int cc = i - 9;
            su[cc] = scale * (__ldg(bq+0)*__ldg(Wk+cc)
                            + __ldg(bq+1)*__ldg(Wk+3+cc)
                            + __ldg(bq+2)*__ldg(Wk+6+cc));
        } else if (i < 15) {
            int cc = i - 12;
            swb[cc] = scale * (__ldg(bk+0)*__ldg(Wq+cc)
                             + __ldg(bk+1)*__ldg(Wq+3+cc)
                             + __ldg(bk+2)*__ldg(Wq+6+cc));
        } else if (i == 15) {
            s_s0 = scale * (__ldg(bk+0)*__ldg(bq+0)
                          + __ldg(bk+1)*__ldg(bq+1)
                          + __ldg(bk+2)*__ldg(bq+2));
        } else if (i < 25) {
            int r = (i - 16) / 3, cc = (i - 16) % 3;
            sNw[i-16] = __ldg(Wo+r*3+0)*__ldg(Wv+cc)
                      + __ldg(Wo+r*3+1)*__ldg(Wv+3+cc)
                      + __ldg(Wo+r*3+2)*__ldg(Wv+6+cc);
        } else {
            int r = i - 25;
            sp[r] = __ldg(Wo+r*3+0)*__ldg(bv+0)
                  + __ldg(Wo+r*3+1)*__ldg(bv+1)
                  + __ldg(Wo+r*3+2)*__ldg(bv+2) + __ldg(bo+r);
        }
    }
    __syncthreads();

    const int cnt = min(s_cnt, CAP);
    const int qn  = s_qn;
    if (qn == 0) return;

    const float b20 = __ldg(b2 + 0), b21 = __ldg(b2 + 1), b22 = __ldg(b2 + 2);

    // Two queries per warp per round (shared smem loads)
    for (int qq = warp * 2; qq < qn; qq += 16) {
        const int  e0   = sq[qq];
        const bool has2 = (qq + 1) < qn;
        const int  e1   = has2 ? sq[qq + 1] : e0;
        const int  n0q  = e0 & 0xFFFF, p0 = e0 >> 16;
        const int  n1q  = e1 & 0xFFFF, p1 = e1 >> 16;

        float4 xqa, xqb;
        if (p0 < CAP) xqa = sx[p0];
        else { const float* xv = xb + (size_t)n0q * 3; xqa = make_float4(xv[0], xv[1], xv[2], 0.f); }
        if (p1 < CAP) xqb = sx[p1];
        else { const float* xv = xb + (size_t)n1q * 3; xqb = make_float4(xv[0], xv[1], xv[2], 0.f); }

        const float qkA0 = fmaf(sM[0], xqa.x, fmaf(sM[1], xqa.y, fmaf(sM[2], xqa.z, su[0])));
        const float qkA1 = fmaf(sM[3], xqa.x, fmaf(sM[4], xqa.y, fmaf(sM[5], xqa.z, su[1])));
        const float qkA2 = fmaf(sM[6], xqa.x, fmaf(sM[7], xqa.y, fmaf(sM[8], xqa.z, su[2])));
        const float qbA  = fmaf(swb[0], xqa.x, fmaf(swb[1], xqa.y, fmaf(swb[2], xqa.z, s_s0)));
        const float qkB0 = fmaf(sM[0], xqb.x, fmaf(sM[1], xqb.y, fmaf(sM[2], xqb.z, su[0])));
        const float qkB1 = fmaf(sM[3], xqb.x, fmaf(sM[4], xqb.y, fmaf(sM[5], xqb.z, su[1])));
        const float qkB2 = fmaf(sM[6], xqb.x, fmaf(sM[7], xqb.y, fmaf(sM[8], xqb.z, su[2])));
        const float qbB  = fmaf(swb[0], xqb.x, fmaf(swb[1], xqb.y, fmaf(swb[2], xqb.z, s_s0)));

        // dual plain-exp softmax; one sx load feeds both queries
        float smA = 0.f, aA0 = 0.f, aA1 = 0.f, aA2 = 0.f;
        float smB = 0.f, aB0 = 0.f, aB1 = 0.f, aB2 = 0.f;
        for (int i = lane; i < cnt; i += 32) {
            const float4 xm = sx[i];
            const float sA = fmaf(qkA0, xm.x, fmaf(qkA1, xm.y, fmaf(qkA2, xm.z, qbA)));
            const float sB = fmaf(qkB0, xm.x, fmaf(qkB1, xm.y, fmaf(qkB2, xm.z, qbB)));
            const float eA = __expf(sA);
            const float eB = __expf(sB);
            smA += eA; smB += eB;
            aA0 = fmaf(eA, xm.x, aA0); aB0 = fmaf(eB, xm.x, aB0);
            aA1 = fmaf(eA, xm.y, aA1); aB1 = fmaf(eB, xm.y, aB1);
            aA2 = fmaf(eA, xm.z, aA2); aB2 = fmaf(eB, xm.z, aB2);
        }
#pragma unroll
        for (int off = 16; off; off >>= 1) {
            smA += __shfl_down_sync(0xffffffffu, smA, off);
            aA0 += __shfl_down_sync(0xffffffffu, aA0, off);
            aA1 += __shfl_down_sync(0xffffffffu, aA1, off);
            aA2 += __shfl_down_sync(0xffffffffu, aA2, off);
            smB += __shfl_down_sync(0xffffffffu, smB, off);
            aB0 += __shfl_down_sync(0xffffffffu, aB0, off);
            aB1 += __shfl_down_sync(0xffffffffu, aB1, off);
            aB2 += __shfl_down_sync(0xffffffffu, aB2, off);
        }
        smA = __shfl_sync(0xffffffffu, smA, 0);
        aA0 = __shfl_sync(0xffffffffu, aA0, 0);
        aA1 = __shfl_sync(0xffffffffu, aA1, 0);
        aA2 = __shfl_sync(0xffffffffu, aA2, 0);
        smB = __shfl_sync(0xffffffffu, smB, 0);
        aB0 = __shfl_sync(0xffffffffu, aB0, 0);
        aB1 = __shfl_sync(0xffffffffu, aB1, 0);
        aB2 = __shfl_sync(0xffffffffu, aB2, 0);

        const float invA = 1.f / smA, invB = 1.f / smB;
        const float mA0 = aA0 * invA, mA1 = aA1 * invA, mA2 = aA2 * invA;
        const float mB0 = aB0 * invB, mB1 = aB1 * invB, mB2 = aB2 * invB;

        const float oA0 = fmaf(sNw[0], mA0, fmaf(sNw[1], mA1, fmaf(sNw[2], mA2, sp[0])));
        const float oA1 = fmaf(sNw[3], mA0, fmaf(sNw[4], mA1, fmaf(sNw[5], mA2, sp[1])));
        const float oA2 = fmaf(sNw[6], mA0, fmaf(sNw[7], mA1, fmaf(sNw[8], mA2, sp[2])));
        const float oB0 = fmaf(sNw[0], mB0, fmaf(sNw[1], mB1, fmaf(sNw[2], mB2, sp[0])));
        const float oB1 = fmaf(sNw[3], mB0, fmaf(sNw[4], mB1, fmaf(sNw[5], mB2, sp[1])));
        const float oB2 = fmaf(sNw[6], mB0, fmaf(sNw[7], mB1, fmaf(sNw[8], mB2, sp[2])));

        // dual MLP: packed float4 weights -> 2 LDS.128 per iter, no addr math
        float yA0 = 0.f, yA1 = 0.f, yA2 = 0.f;
        float yB0 = 0.f, yB1 = 0.f, yB2 = 0.f;
#pragma unroll
        for (int t = 0; t < HH / 32; t++) {
            const int j = lane + t * 32;
            const float4 w = sW1p[j];
            float hA = fmaf(w.x, oA0, fmaf(w.y, oA1, fmaf(w.z, oA2, w.w)));
            float hB = fmaf(w.x, oB0, fmaf(w.y, oB1, fmaf(w.z, oB2, w.w)));
            hA = fmaxf(hA, 0.f); hB = fmaxf(hB, 0.f);
            const float4 u = sW2p[j];
            yA0 = fmaf(u.x, hA, yA0); yB0 = fmaf(u.x, hB, yB0);
            yA1 = fmaf(u.y, hA, yA1); yB1 = fmaf(u.y, hB, yB1);
            yA2 = fmaf(u.z, hA, yA2); yB2 = fmaf(u.z, hB, yB2);
        }
#pragma unroll
        for (int off = 16; off; off >>= 1) {
            yA0 += __shfl_down_sync(0xffffffffu, yA0, off);
            yA1 += __shfl_down_sync(0xffffffffu, yA1, off);
            yA2 += __shfl_down_sync(0xffffffffu, yA2, off);
            yB0 += __shfl_down_sync(0xffffffffu, yB0, off);
            yB1 += __shfl_down_sync(0xffffffffu, yB1, off);
            yB2 += __shfl_down_sync(0xffffffffu, yB2, off);
        }
        if (lane == 0) {
            float* op = out + (size_t)(b * KOUT + n0q) * 3;
            op[0] = yA0 + b20; op[1] = yA1 + b21; op[2] = yA2 + b22;
            if (has2) {
                float* oq = out + (size_t)(b * KOUT + n1q) * 3;
                oq[0] = yB0 + b20; oq[1] = yB1 + b21; oq[2] = yB2 + b22;
            }
        }
    }
}

// ---------------------------------------------------------------------------
extern "C" void kernel_launch(void* const* d_in, const int* in_sizes, int n_in,
                              void* d_out, int out_size)
{
    const float* x      = (const float*)d_in[0];
    const int*   labels = (const int*)  d_in[1];
    const float* Wq = (const float*)d_in[2];
    const float* bq = (const float*)d_in[3];
    const float* Wk = (const float*)d_in[4];
    const float* bk = (const float*)d_in[5];
    const float* Wv = (const float*)d_in[6];
    const float* bv = (const float*)d_in[7];
    const float* Wo = (const float*)d_in[8];
    const float* bo = (const float*)d_in[9];
    const float* W1 = (const float*)d_in[10];
    const float* b1 = (const float*)d_in[11];
    const float* W2 = (const float*)d_in[12];
    const float* b2 = (const float*)d_in[13];
    float* out = (float*)d_out;

    fused_kernel<<<BATCH * 64, 256>>>(x, labels, Wq, bq, Wk, bk, Wv, bv,
                                      Wo, bo, W1, b1, W2, b2, out);
}

// round 12
// speedup vs baseline: 2.2079x; 1.0500x over previous
#include <cuda_runtime.h>
#include <math.h>

#define BATCH 8
#define NPTS  4096
#define HH    256
#define KOUT  1024
#define NC    63
#define CAP   512           // smem member capacity (E[cnt]=64 -> 50+ sigma margin)

// ---------------------------------------------------------------------------
// Single kernel. Block (b,c): c in [0,63) = cluster block, c==63 = noise rows.
// Phase 1: branch-light bitmask scan -> member index list (ints only).
// Phase 2: parallel scattered gather of member x into smem + query collection.
// Phase 3: dual-query warp attention (pre-folded weights) + packed-f4 MLP.
//   score(x_m) = qk·x_m + qb,   qk = M·x_q + u,  qb = wb·x_q + s0
//   o          = N·mean + p     (k/v/ctx never materialized)
// ---------------------------------------------------------------------------
__global__ __launch_bounds__(256, 4)
void fused_kernel(const float* __restrict__ x,
                  const int*   __restrict__ labels,
                  const float* __restrict__ Wq, const float* __restrict__ bq,
                  const float* __restrict__ Wk, const float* __restrict__ bk,
                  const float* __restrict__ Wv, const float* __restrict__ bv,
                  const float* __restrict__ Wo, const float* __restrict__ bo,
                  const float* __restrict__ W1, const float* __restrict__ b1,
                  const float* __restrict__ W2, const float* __restrict__ b2,
                  float* __restrict__ out)
{
    __shared__ float4 sx[CAP];            // member x (w unused)
    __shared__ short  smidx[CAP];         // member original row n (0..4095)
    __shared__ int    sq[CAP];            // (sx pos << 16) | query row n
    __shared__ float4 sW1p[HH];           // (W1[3j], W1[3j+1], W1[3j+2], b1[j])
    __shared__ float4 sW2p[HH];           // (W2[j], W2[HH+j], W2[2HH+j], 0)
    __shared__ float  sM[9], su[3], swb[3], sNw[9], sp[3], s_s0;
    __shared__ int    s_cnt, s_qn;
    __shared__ float  s_y3[3];

    const int tid  = threadIdx.x;
    const int warp = tid >> 5;
    const int lane = tid & 31;
    const int b    = blockIdx.x >> 6;
    const int c    = blockIdx.x & 63;

    const int*   lab = labels + b * NPTS;
    const float* xb  = x + (size_t)b * NPTS * 3;

    // Stage MLP weights packed (one j per thread; 256 == HH)
    {
        const int j = tid;
        sW1p[j] = make_float4(W1[3*j], W1[3*j+1], W1[3*j+2], b1[j]);
        sW2p[j] = make_float4(W2[j], W2[HH + j], W2[2*HH + j], 0.f);
    }

    // ---------------- noise block: constant output for label==-1 rows --------
    if (c == NC) {
        __syncthreads();
        if (warp == 0) {
            float o0 = __ldg(bo + 0), o1 = __ldg(bo + 1), o2 = __ldg(bo + 2);
            float y0 = 0.f, y1 = 0.f, y2 = 0.f;
#pragma unroll
            for (int t = 0; t < HH / 32; t++) {
                int j = lane + t * 32;
                float4 w = sW1p[j];
                float h = fmaf(w.x, o0, fmaf(w.y, o1, fmaf(w.z, o2, w.w)));
                h = fmaxf(h, 0.f);
                float4 u = sW2p[j];
                y0 = fmaf(u.x, h, y0);
                y1 = fmaf(u.y, h, y1);
                y2 = fmaf(u.z, h, y2);
            }
#pragma unroll
            for (int off = 16; off; off >>= 1) {
                y0 += __shfl_down_sync(0xffffffffu, y0, off);
                y1 += __shfl_down_sync(0xffffffffu, y1, off);
                y2 += __shfl_down_sync(0xffffffffu, y2, off);
            }
            if (lane == 0) {
                s_y3[0] = y0 + __ldg(b2 + 0);
                s_y3[1] = y1 + __ldg(b2 + 1);
                s_y3[2] = y2 + __ldg(b2 + 2);
            }
        }
        __syncthreads();
        float y0 = s_y3[0], y1 = s_y3[1], y2 = s_y3[2];
        const int4 L = reinterpret_cast<const int4*>(lab)[tid];
        const int n0 = tid * 4;
        if (L.x == -1) { float* op = out + (size_t)(b*KOUT + n0    )*3; op[0]=y0; op[1]=y1; op[2]=y2; }
        if (L.y == -1) { float* op = out + (size_t)(b*KOUT + n0 + 1)*3; op[0]=y0; op[1]=y1; op[2]=y2; }
        if (L.z == -1) { float* op = out + (size_t)(b*KOUT + n0 + 2)*3; op[0]=y0; op[1]=y1; op[2]=y2; }
        if (L.w == -1) { float* op = out + (size_t)(b*KOUT + n0 + 3)*3; op[0]=y0; op[1]=y1; op[2]=y2; }
        return;
    }

    // ---------------- cluster block ----------------
    if (tid == 0) { s_cnt = 0; s_qn = 0; }
    __syncthreads();

    // Phase 1: branchless bitmask scan (bit bi = t*4+j -> row t*1024 + tid*4 + j)
    const int4* lab4 = reinterpret_cast<const int4*>(lab);
    unsigned mask = 0;
#pragma unroll
    for (int t = 0; t < 4; t++) {
        const int4 L = lab4[t * 256 + tid];
        mask |= (unsigned)(L.x == c) << (t * 4 + 0);
        mask |= (unsigned)(L.y == c) << (t * 4 + 1);
        mask |= (unsigned)(L.z == c) << (t * 4 + 2);
        mask |= (unsigned)(L.w == c) << (t * 4 + 3);
    }
    const int nbase = tid * 4;
    while (mask) {
        const int bi = __ffs(mask) - 1;
        mask &= mask - 1;
        const int n = ((bi >> 2) << 10) + nbase + (bi & 3);
        const int p = atomicAdd(&s_cnt, 1);
        if (p < CAP) smidx[p] = (short)n;
    }

    // Parallel prefold: 28 threads, one folded scalar each.
    if (tid < 28) {
        const float scale = 0.57735026919f;   // 1/sqrt(3)
        const int i = tid;
        if (i < 9) {
            int cc = i / 3, d = i % 3;
            sM[i] = scale * (__ldg(Wq+d)  *__ldg(Wk+cc)
                           + __ldg(Wq+3+d)*__ldg(Wk+3+cc)
                           + __ldg(Wq+6+d)*__ldg(Wk+6+cc));
        } else if (i < 12) {
            int cc = i - 9;
            su[cc] = scale * (__ldg(bq+0)*__ldg(Wk+cc)
                            + __ldg(bq+1)*__ldg(Wk+3+cc)
                            + __ldg(bq+2)*__ldg(Wk+6+cc));
        } else if (i < 15) {
            int cc = i - 12;
            swb[cc] = scale * (__ldg(bk+0)*__ldg(Wq+cc)
                             + __ldg(bk+1)*__ldg(Wq+3+cc)
                             + __ldg(bk+2)*__ldg(Wq+6+cc));
        } else if (i == 15) {
            s_s0 = scale * (__ldg(bk+0)*__ldg(bq+0)
                          + __ldg(bk+1)*__ldg(bq+1)
                          + __ldg(bk+2)*__ldg(bq+2));
        } else if (i < 25) {
            int r = (i - 16) / 3, cc = (i - 16) % 3;
            sNw[i-16] = __ldg(Wo+r*3+0)*__ldg(Wv+cc)
                      + __ldg(Wo+r*3+1)*__ldg(Wv+3+cc)
                      + __ldg(Wo+r*3+2)*__ldg(Wv+6+cc);
        } else {
            int r = i - 25;
            sp[r] = __ldg(Wo+r*3+0)*__ldg(bv+0)
                  + __ldg(Wo+r*3+1)*__ldg(bv+1)
                  + __ldg(Wo+r*3+2)*__ldg(bv+2) + __ldg(bo+r);
        }
    }
    __syncthreads();

    const int cnt = min(s_cnt, CAP);

    // Phase 2: parallel gather of member x + query collection (cnt < 256 typ.)
    for (int i = tid; i < cnt; i += 256) {
        const int n = smidx[i];
        const float* xv = xb + (size_t)n * 3;
        sx[i] = make_float4(xv[0], xv[1], xv[2], 0.f);
        if (n < KOUT) {
            int qp = atomicAdd(&s_qn, 1);
            sq[qp] = n | (i << 16);
        }
    }
    __syncthreads();

    const int qn = s_qn;
    if (qn == 0) return;

    const float b20 = __ldg(b2 + 0), b21 = __ldg(b2 + 1), b22 = __ldg(b2 + 2);

    // Phase 3: two queries per warp per round (shared smem loads)
    for (int qq = warp * 2; qq < qn; qq += 16) {
        const int  e0   = sq[qq];
        const bool has2 = (qq + 1) < qn;
        const int  e1   = has2 ? sq[qq + 1] : e0;
        const int  n0q  = e0 & 0xFFFF, p0 = e0 >> 16;
        const int  n1q  = e1 & 0xFFFF, p1 = e1 >> 16;

        const float4 xqa = sx[p0];
        const float4 xqb = sx[p1];

        const float qkA0 = fmaf(sM[0], xqa.x, fmaf(sM[1], xqa.y, fmaf(sM[2], xqa.z, su[0])));
        const float qkA1 = fmaf(sM[3], xqa.x, fmaf(sM[4], xqa.y, fmaf(sM[5], xqa.z, su[1])));
        const float qkA2 = fmaf(sM[6], xqa.x, fmaf(sM[7], xqa.y, fmaf(sM[8], xqa.z, su[2])));
        const float qbA  = fmaf(swb[0], xqa.x, fmaf(swb[1], xqa.y, fmaf(swb[2], xqa.z, s_s0)));
        const float qkB0 = fmaf(sM[0], xqb.x, fmaf(sM[1], xqb.y, fmaf(sM[2], xqb.z, su[0])));
        const float qkB1 = fmaf(sM[3], xqb.x, fmaf(sM[4], xqb.y, fmaf(sM[5], xqb.z, su[1])));
        const float qkB2 = fmaf(sM[6], xqb.x, fmaf(sM[7], xqb.y, fmaf(sM[8], xqb.z, su[2])));
        const float qbB  = fmaf(swb[0], xqb.x, fmaf(swb[1], xqb.y, fmaf(swb[2], xqb.z, s_s0)));

        // dual plain-exp softmax; one sx load feeds both queries
        float smA = 0.f, aA0 = 0.f, aA1 = 0.f, aA2 = 0.f;
        float smB = 0.f, aB0 = 0.f, aB1 = 0.f, aB2 = 0.f;
        for (int i = lane; i < cnt; i += 32) {
            const float4 xm = sx[i];
            const float sA = fmaf(qkA0, xm.x, fmaf(qkA1, xm.y, fmaf(qkA2, xm.z, qbA)));
            const float sB = fmaf(qkB0, xm.x, fmaf(qkB1, xm.y, fmaf(qkB2, xm.z, qbB)));
            const float eA = __expf(sA);
            const float eB = __expf(sB);
            smA += eA; smB += eB;
            aA0 = fmaf(eA, xm.x, aA0); aB0 = fmaf(eB, xm.x, aB0);
            aA1 = fmaf(eA, xm.y, aA1); aB1 = fmaf(eB, xm.y, aB1);
            aA2 = fmaf(eA, xm.z, aA2); aB2 = fmaf(eB, xm.z, aB2);
        }
#pragma unroll
        for (int off = 16; off; off >>= 1) {
            smA += __shfl_down_sync(0xffffffffu, smA, off);
            aA0 += __shfl_down_sync(0xffffffffu, aA0, off);
            aA1 += __shfl_down_sync(0xffffffffu, aA1, off);
            aA2 += __shfl_down_sync(0xffffffffu, aA2, off);
            smB += __shfl_down_sync(0xffffffffu, smB, off);
            aB0 += __shfl_down_sync(0xffffffffu, aB0, off);
            aB1 += __shfl_down_sync(0xffffffffu, aB1, off);
            aB2 += __shfl_down_sync(0xffffffffu, aB2, off);
        }
        smA = __shfl_sync(0xffffffffu, smA, 0);
        aA0 = __shfl_sync(0xffffffffu, aA0, 0);
        aA1 = __shfl_sync(0xffffffffu, aA1, 0);
        aA2 = __shfl_sync(0xffffffffu, aA2, 0);
        smB = __shfl_sync(0xffffffffu, smB, 0);
        aB0 = __shfl_sync(0xffffffffu, aB0, 0);
        aB1 = __shfl_sync(0xffffffffu, aB1, 0);
        aB2 = __shfl_sync(0xffffffffu, aB2, 0);

        const float invA = 1.f / smA, invB = 1.f / smB;
        const float mA0 = aA0 * invA, mA1 = aA1 * invA, mA2 = aA2 * invA;
        const float mB0 = aB0 * invB, mB1 = aB1 * invB, mB2 = aB2 * invB;

        const float oA0 = fmaf(sNw[0], mA0, fmaf(sNw[1], mA1, fmaf(sNw[2], mA2, sp[0])));
        const float oA1 = fmaf(sNw[3], mA0, fmaf(sNw[4], mA1, fmaf(sNw[5], mA2, sp[1])));
        const float oA2 = fmaf(sNw[6], mA0, fmaf(sNw[7], mA1, fmaf(sNw[8], mA2, sp[2])));
        const float oB0 = fmaf(sNw[0], mB0, fmaf(sNw[1], mB1, fmaf(sNw[2], mB2, sp[0])));
        const float oB1 = fmaf(sNw[3], mB0, fmaf(sNw[4], mB1, fmaf(sNw[5], mB2, sp[1])));
        const float oB2 = fmaf(sNw[6], mB0, fmaf(sNw[7], mB1, fmaf(sNw[8], mB2, sp[2])));

        // dual MLP: packed float4 weights -> 2 LDS.128 per iter, no addr math
        float yA0 = 0.f, yA1 = 0.f, yA2 = 0.f;
        float yB0 = 0.f, yB1 = 0.f, yB2 = 0.f;
#pragma unroll
        for (int t = 0; t < HH / 32; t++) {
            const int j = lane + t * 32;
            const float4 w = sW1p[j];
            float hA = fmaf(w.x, oA0, fmaf(w.y, oA1, fmaf(w.z, oA2, w.w)));
            float hB = fmaf(w.x, oB0, fmaf(w.y, oB1, fmaf(w.z, oB2, w.w)));
            hA = fmaxf(hA, 0.f); hB = fmaxf(hB, 0.f);
            const float4 u = sW2p[j];
            yA0 = fmaf(u.x, hA, yA0); yB0 = fmaf(u.x, hB, yB0);
            yA1 = fmaf(u.y, hA, yA1); yB1 = fmaf(u.y, hB, yB1);
            yA2 = fmaf(u.z, hA, yA2); yB2 = fmaf(u.z, hB, yB2);
        }
#pragma unroll
        for (int off = 16; off; off >>= 1) {
            yA0 += __shfl_down_sync(0xffffffffu, yA0, off);
            yA1 += __shfl_down_sync(0xffffffffu, yA1, off);
            yA2 += __shfl_down_sync(0xffffffffu, yA2, off);
            yB0 += __shfl_down_sync(0xffffffffu, yB0, off);
            yB1 += __shfl_down_sync(0xffffffffu, yB1, off);
            yB2 += __shfl_down_sync(0xffffffffu, yB2, off);
        }
        if (lane == 0) {
            float* op = out + (size_t)(b * KOUT + n0q) * 3;
            op[0] = yA0 + b20; op[1] = yA1 + b21; op[2] = yA2 + b22;
            if (has2) {
                float* oq = out + (size_t)(b * KOUT + n1q) * 3;
                oq[0] = yB0 + b20; oq[1] = yB1 + b21; oq[2] = yB2 + b22;
            }
        }
    }
}

// ---------------------------------------------------------------------------
extern "C" void kernel_launch(void* const* d_in, const int* in_sizes, int n_in,
                              void* d_out, int out_size)
{
    const float* x      = (const float*)d_in[0];
    const int*   labels = (const int*)  d_in[1];
    const float* Wq = (const float*)d_in[2];
    const float* bq = (const float*)d_in[3];
    const float* Wk = (const float*)d_in[4];
    const float* bk = (const float*)d_in[5];
    const float* Wv = (const float*)d_in[6];
    const float* bv = (const float*)d_in[7];
    const float* Wo = (const float*)d_in[8];
    const float* bo = (const float*)d_in[9];
    const float* W1 = (const float*)d_in[10];
    const float* b1 = (const float*)d_in[11];
    const float* W2 = (const float*)d_in[12];
    const float* b2 = (const float*)d_in[13];
    float* out = (float*)d_out;

    fused_kernel<<<BATCH * 64, 256>>>(x, labels, Wq, bq, Wk, bk, Wv, bv,
                                      Wo, bo, W1, b1, W2, b2, out);
}